// round 13
// baseline (speedup 1.0000x reference)
#include <cuda_runtime.h>
#include <cuda_bf16.h>
#include <math_constants.h>

// ProbAttention (Informer ProbSparse) — B=4, L=S=2048, H=8, D=64, sample_k=n_top=40.
// Inputs: queries f32 [B,L,H,D], keys f32 [B,S,H,D], values f32 [B,S,H,D],
//         index_sample i32 [L,40].  Output f32 [B,L,H,D].

#define B_ 4
#define L_ 2048
#define S_ 2048
#define H_ 8
#define D_ 64
#define SK_ 40
#define NTOP_ 40
#define BH_ (B_ * H_)
#define SCALE_ 0.125f
#define QPB_ 10
#define QBLKS_ (NTOP_ / QPB_)        // 4

#define CHUNK_ 256
#define NCHUNK_ (L_ / CHUNK_)        // 8
#define NBUCK_ (NCHUNK_ * S_)        // 16384
#define NPAIR_ (L_ * SK_)            // 81920
#define TILE_S_ 128
#define ATILE_ 256

// Scratch
__device__ int   g_off[NBUCK_ + 1];
__device__ int   g_pairs[NPAIR_];    // packed (s<<11)|l
__device__ float g_M[BH_ * L_];
__device__ int   g_top[BH_ * NTOP_];
__device__ float g_vmean[BH_ * D_];

// Order-preserving float<->uint (for smem atomicMax on floats)
__device__ __forceinline__ unsigned ford(float f) {
    unsigned u = __float_as_uint(f);
    return (u & 0x80000000u) ? ~u : (u | 0x80000000u);
}
__device__ __forceinline__ float funord(unsigned u) {
    u = (u & 0x80000000u) ? (u & 0x7FFFFFFFu) : ~u;
    return __uint_as_float(u);
}

// Packed f32x2 helpers (Blackwell)
__device__ __forceinline__ unsigned long long ffma2(unsigned long long a,
                                                    unsigned long long b,
                                                    unsigned long long c) {
    unsigned long long d;
    asm("fma.rn.f32x2 %0, %1, %2, %3;" : "=l"(d) : "l"(a), "l"(b), "l"(c));
    return d;
}
__device__ __forceinline__ unsigned long long f2u(float lo, float hi) {
    unsigned long long r;
    asm("mov.b64 %0, {%1, %2};" : "=l"(r) : "f"(lo), "f"(hi));
    return r;
}
__device__ __forceinline__ float f32x2_sum(unsigned long long v) {
    float lo, hi;
    asm("mov.b64 {%0, %1}, %2;" : "=f"(lo), "=f"(hi) : "l"(v));
    return lo + hi;
}

// ---------------------------------------------------------------------------
// K_index: ONE block builds the whole inverse index.
// smem hist -> smem scan -> scatter (offsets double as pos counters).
// ---------------------------------------------------------------------------
#define SMEM_INDEX_ ((NBUCK_ + 1024) * 4)

__global__ __launch_bounds__(1024) void k_index(const int* __restrict__ idxs) {
    extern __shared__ int ish[];
    int* hist = ish;             // [NBUCK_]
    int* sums = ish + NBUCK_;    // [1024]
    const int t = threadIdx.x;

    for (int i = t; i < NBUCK_; i += 1024) hist[i] = 0;
    __syncthreads();

    for (int i = t; i < NPAIR_; i += 1024) {
        int l = i / SK_;
        int s = idxs[i];
        atomicAdd(&hist[(l >> 8) * S_ + s], 1);
    }
    __syncthreads();

    int base = t * 16;
    int loc[16];
    int run = 0;
    #pragma unroll
    for (int j = 0; j < 16; j++) { loc[j] = run; run += hist[base + j]; }
    sums[t] = run;
    __syncthreads();
    for (int off = 1; off < 1024; off <<= 1) {
        int v = (t >= off) ? sums[t - off] : 0;
        __syncthreads();
        sums[t] += v;
        __syncthreads();
    }
    int myoff = t ? sums[t - 1] : 0;
    #pragma unroll
    for (int j = 0; j < 16; j++) {
        int o = myoff + loc[j];
        g_off[base + j] = o;
        hist[base + j] = o;        // becomes live position counter
    }
    if (t == 1023) g_off[NBUCK_] = sums[1023];
    __syncthreads();

    for (int i = t; i < NPAIR_; i += 1024) {
        int l = i / SK_;
        int s = idxs[i];
        int pos = atomicAdd(&hist[(l >> 8) * S_ + s], 1);
        g_pairs[pos] = (s << 11) | l;
    }
}

// ---------------------------------------------------------------------------
// K1 (s-major): block = (b,h,chunk). Q-chunk in smem; K streamed in tiles;
// pair list drives LDS + FFMA2 dots; per-l max/sum via smem atomics.
// ---------------------------------------------------------------------------
#define SMEM_SAMPLE_ (CHUNK_ * D_ * 4 + TILE_S_ * D_ * 4 + CHUNK_ * 8)

__global__ __launch_bounds__(256) void k_sample(const float* __restrict__ q,
                                                const float* __restrict__ k) {
    extern __shared__ float dyn[];
    float*    q_s   = dyn;                                   // [CHUNK_][64] swizzled
    float*    k_t   = dyn + CHUNK_ * D_;                     // [TILE_S_][64] swizzled
    unsigned* m_max = (unsigned*)(k_t + TILE_S_ * D_);       // [CHUNK_]
    float*    m_sum = (float*)(m_max + CHUNK_);              // [CHUNK_]

    const int bhc = blockIdx.x;
    const int c = bhc & 7, h = (bhc >> 3) & 7, b = bhc >> 6;
    const int t = threadIdx.x;

    if (t < CHUNK_) { m_max[t] = ford(-CUDART_INF_F); m_sum[t] = 0.f; }

    {
        const float4* qg = (const float4*)q;
        for (int i = t; i < CHUNK_ * 16; i += 256) {
            int l = i >> 4, j = i & 15;
            float4 v = qg[(size_t)((b * L_ + (c * CHUNK_ + l)) * H_ + h) * 16 + j];
            ((float4*)q_s)[l * 16 + (j ^ (l & 7))] = v;
        }
    }

    const float4* kg = (const float4*)k;
    for (int s0 = 0; s0 < S_; s0 += TILE_S_) {
        __syncthreads();
        for (int i = t; i < TILE_S_ * 16; i += 256) {
            int sr = i >> 4, j = i & 15;
            float4 v = kg[(size_t)((b * S_ + (s0 + sr)) * H_ + h) * 16 + j];
            ((float4*)k_t)[sr * 16 + (j ^ (sr & 7))] = v;
        }
        __syncthreads();

        int base = g_off[c * S_ + s0];
        int end  = g_off[c * S_ + s0 + TILE_S_];
        for (int e = base + t; e < end; e += 256) {
            int pk = g_pairs[e];
            int lr = pk & (CHUNK_ - 1);
            int sr = (pk >> 11) & (TILE_S_ - 1);
            const ulonglong2* qr = (const ulonglong2*)q_s + lr * 16;
            const ulonglong2* kr = (const ulonglong2*)k_t + sr * 16;
            unsigned long long a2 = 0ull;
            #pragma unroll
            for (int j = 0; j < 16; j++) {
                ulonglong2 a  = qr[j ^ (lr & 7)];
                ulonglong2 bb = kr[j ^ (sr & 7)];
                a2 = ffma2(a.x, bb.x, a2);
                a2 = ffma2(a.y, bb.y, a2);
            }
            float acc = f32x2_sum(a2);
            atomicMax(&m_max[lr], ford(acc));
            atomicAdd(&m_sum[lr], acc);
        }
    }
    __syncthreads();

    if (t < CHUNK_) {
        float mx = funord(m_max[t]);
        g_M[(size_t)(b * H_ + h) * L_ + c * CHUNK_ + t] =
            mx - m_sum[t] * (1.0f / (float)S_);
    }
}

// ---------------------------------------------------------------------------
// K2: top-40 per (b,h). One WARP per bh; 64 vals/lane register-resident;
// iterative argmax via 64-bit shuffle keys; deletion via per-lane bitmask.
// Tie -> smaller global index (matches jax.lax.top_k).
// ---------------------------------------------------------------------------
__global__ __launch_bounds__(512) void k_topk() {
    const int w = (blockIdx.x << 4) + (threadIdx.x >> 5);  // bh 0..31
    const int lane = threadIdx.x & 31;

    float vals[64];
    #pragma unroll
    for (int j = 0; j < 64; j++)
        vals[j] = g_M[(size_t)w * L_ + j * 32 + lane];

    unsigned long long mask = 0ull;
    float bv = -CUDART_INF_F; int bj = 0;
    #pragma unroll
    for (int j = 0; j < 64; j++)
        if (vals[j] > bv) { bv = vals[j]; bj = j; }

    for (int it = 0; it < NTOP_; it++) {
        unsigned long long key =
            ((unsigned long long)ford(bv) << 32) |
            (unsigned)~(unsigned)(bj * 32 + lane);
        #pragma unroll
        for (int o = 16; o; o >>= 1) {
            unsigned long long ot = __shfl_xor_sync(0xFFFFFFFFu, key, o);
            if (ot > key) key = ot;
        }
        unsigned widx = ~(unsigned)(key & 0xFFFFFFFFu);
        if (lane == 0) g_top[w * NTOP_ + it] = (int)widx;
        if ((widx & 31u) == (unsigned)lane) {
            mask |= 1ull << (widx >> 5);
            bv = -CUDART_INF_F; bj = 0;
            #pragma unroll
            for (int j = 0; j < 64; j++)
                if (!((mask >> j) & 1ull) && vals[j] > bv) { bv = vals[j]; bj = j; }
        }
    }
}

// ---------------------------------------------------------------------------
// K3: vmean[bh, d] = mean_s v[b,s,h,d]  (32 blocks, no atomics)
// ---------------------------------------------------------------------------
__global__ void k_vmean(const float* __restrict__ v) {
    int bh = blockIdx.x;
    int b = bh >> 3, h = bh & 7;
    int tid = threadIdx.x;
    int d = tid & 63, g = tid >> 6;
    float s = 0.f;
    #pragma unroll 4
    for (int r = g; r < S_; r += 4)
        s += v[(((size_t)(b * S_ + r)) * H_ + h) * D_ + d];
    __shared__ float part[4][D_];
    part[g][d] = s;
    __syncthreads();
    if (g == 0)
        g_vmean[bh * D_ + d] =
            (part[0][d] + part[1][d] + part[2][d] + part[3][d]) * (1.0f / (float)S_);
}

// ---------------------------------------------------------------------------
// K4: out[b,l,h,d] = vmean[bh,d]
// ---------------------------------------------------------------------------
__global__ void k_fill(float4* __restrict__ out) {
    unsigned i = blockIdx.x * blockDim.x + threadIdx.x;
    if (i >= (unsigned)(B_ * L_ * H_ * (D_ / 4))) return;
    unsigned d4 = i & 15u;
    unsigned h  = (i >> 4) & 7u;
    unsigned b  = i >> 18;
    const float4* vm = (const float4*)g_vmean;
    out[i] = __ldg(vm + ((b * H_ + h) * (D_ / 4) + d4));
}

// ---------------------------------------------------------------------------
// K5: dense attention, 10 queries/block, 128 blocks (<=1 wave).
// Scores: smem-tiled K + f32x2 FFMA. AV: s-paired f32x2.
// Dyn smem: k_t 64KB + sc 80KB = 147456 B.
// ---------------------------------------------------------------------------
#define SMEM_ATTN_ ((ATILE_ * D_ + QPB_ * S_) * 4)

__global__ __launch_bounds__(256) void k_attn(const float* __restrict__ q,
                                              const float* __restrict__ k,
                                              const float* __restrict__ v,
                                              float* __restrict__ out) {
    extern __shared__ float dyn[];
    float* k_t = dyn;                  // [ATILE_][16 float4] swizzled
    float* sc  = dyn + ATILE_ * D_;    // [QPB_][S_]

    __shared__ __align__(16) float sq[QPB_][D_];
    __shared__ float sZ[QPB_];
    __shared__ int   sl[QPB_];
    __shared__ float pr[4][QPB_][D_];

    const int bh = blockIdx.x >> 2;
    const int qb = blockIdx.x & 3;
    const int b = bh >> 3, h = bh & 7;
    const int tid = threadIdx.x;

    for (int i = tid; i < QPB_ * D_; i += 256) {
        int qi = i >> 6, d = i & 63;
        int lsel = g_top[bh * NTOP_ + qb * QPB_ + qi];
        if (d == 0) sl[qi] = lsel;
        sq[qi][d] = q[(((size_t)(b * L_ + lsel)) * H_ + h) * D_ + d] * SCALE_;
    }
    __syncthreads();

    // Scores
    const float4* kg = (const float4*)k;
    for (int s0 = 0; s0 < S_; s0 += ATILE_) {
        __syncthreads();
        for (int i = tid; i < ATILE_ * 16; i += 256) {
            int r = i >> 4, j = i & 15;
            ((float4*)k_t)[r * 16 + (j ^ (r & 15))] =
                kg[(size_t)((b * S_ + (s0 + r)) * H_ + h) * 16 + j];
        }
        __syncthreads();

        const int r = tid;
        const ulonglong2* kr = (const ulonglong2*)k_t + r * 16;
        unsigned long long acc2[QPB_];
        #pragma unroll
        for (int qi = 0; qi < QPB_; qi++) acc2[qi] = 0ull;
        #pragma unroll
        for (int j = 0; j < 16; j++) {
            ulonglong2 kv = kr[j ^ (r & 15)];
            #pragma unroll
            for (int qi = 0; qi < QPB_; qi++) {
                ulonglong2 q2 = ((const ulonglong2*)sq[qi])[j];
                acc2[qi] = ffma2(q2.x, kv.x, acc2[qi]);
                acc2[qi] = ffma2(q2.y, kv.y, acc2[qi]);
            }
        }
        #pragma unroll
        for (int qi = 0; qi < QPB_; qi++)
            sc[qi * S_ + s0 + r] = f32x2_sum(acc2[qi]);
    }
    __syncthreads();

    // Softmax: warp handles queries w, w+8
    const int w = tid >> 5, lane = tid & 31;
    for (int qi = w; qi < QPB_; qi += 8) {
        float mx = -CUDART_INF_F;
        for (int s = lane; s < S_; s += 32) mx = fmaxf(mx, sc[qi * S_ + s]);
        #pragma unroll
        for (int o = 16; o; o >>= 1) mx = fmaxf(mx, __shfl_xor_sync(0xFFFFFFFFu, mx, o));
        float sum = 0.f;
        for (int s = lane; s < S_; s += 32) {
            float e = __expf(sc[qi * S_ + s] - mx);
            sc[qi * S_ + s] = e;
            sum += e;
        }
        #pragma unroll
        for (int o = 16; o; o >>= 1) sum += __shfl_xor_sync(0xFFFFFFFFu, sum, o);
        if (lane == 0) sZ[qi] = sum;
    }
    __syncthreads();

    // AV: thread = (d, g), g in 0..3; process s-pairs with f32x2.
    const int d = tid & 63, g = tid >> 6;
    unsigned long long av[QPB_];
    #pragma unroll
    for (int qi = 0; qi < QPB_; qi++) av[qi] = 0ull;
    #pragma unroll 4
    for (int s0 = g * 2; s0 < S_; s0 += 8) {
        float v0 = v[(((size_t)(b * S_ + s0)) * H_ + h) * D_ + d];
        float v1 = v[(((size_t)(b * S_ + s0 + 1)) * H_ + h) * D_ + d];
        unsigned long long vv = f2u(v0, v1);
        #pragma unroll
        for (int qi = 0; qi < QPB_; qi++) {
            unsigned long long p2 =
                *(const unsigned long long*)&sc[qi * S_ + s0];
            av[qi] = ffma2(p2, vv, av[qi]);
        }
    }
    #pragma unroll
    for (int qi = 0; qi < QPB_; qi++) pr[g][qi][d] = f32x2_sum(av[qi]);
    __syncthreads();

    for (int i = tid; i < QPB_ * D_; i += 256) {
        int qi = i >> 6, dd = i & 63;
        float r4 = (pr[0][qi][dd] + pr[1][qi][dd] + pr[2][qi][dd] + pr[3][qi][dd])
                   / sZ[qi];
        out[(((size_t)(b * L_ + sl[qi])) * H_ + h) * D_ + dd] = r4;
    }
}

// ---------------------------------------------------------------------------
extern "C" void kernel_launch(void* const* d_in, const int* in_sizes, int n_in,
                              void* d_out, int out_size) {
    const float* q   = (const float*)d_in[0];
    const float* k   = (const float*)d_in[1];
    const float* v   = (const float*)d_in[2];
    const int*   idx = (const int*)d_in[3];
    float* out = (float*)d_out;

    cudaFuncSetAttribute(k_index, cudaFuncAttributeMaxDynamicSharedMemorySize,
                         SMEM_INDEX_);
    cudaFuncSetAttribute(k_sample, cudaFuncAttributeMaxDynamicSharedMemorySize,
                         SMEM_SAMPLE_);
    cudaFuncSetAttribute(k_attn, cudaFuncAttributeMaxDynamicSharedMemorySize,
                         SMEM_ATTN_);

    // 1: vmean   2: fill   3: index   4: sample (ncu capture slot)
    // 5: topk    6: attn
    k_vmean<<<BH_, 256>>>(v);
    {
        unsigned n4 = B_ * L_ * H_ * (D_ / 4);
        k_fill<<<(n4 + 255) / 256, 256>>>((float4*)out);
    }
    k_index<<<1, 1024, SMEM_INDEX_>>>(idx);
    k_sample<<<B_ * H_ * NCHUNK_, 256, SMEM_SAMPLE_>>>(q, k);
    k_topk<<<2, 512>>>();
    k_attn<<<BH_ * QBLKS_, 256, SMEM_ATTN_>>>(q, k, v, out);
}